// round 8
// baseline (speedup 1.0000x reference)
#include <cuda_runtime.h>
#include <math.h>

#define BB 256
#define IND 512
#define OUTD 512
#define ED 256
#define DELTA_C 0.1f
#define LN_EPS_C 1e-5f

typedef unsigned long long u64;

// Scratch (device globals — no allocation allowed)
__device__ float g_Wt[IND * OUTD];         // Wt[i][o] = W[o][i]
__device__ float g_AWt[ED * OUTD];         // AWt[e][o] = attn_w[o][e]
__device__ u64 g_PE2[ED * IND];            // PE2[e][i] = (PE[i][e], PE[i][e])
__device__ float g_scores[IND * OUTD];     // scores[i][o]
__device__ float4 g_WM[IND * (OUTD / 2)];  // (w_lo, w_hi, m_lo, m_hi)

// ---- packed f32x2 helpers (sm_100+; only add/mul/fma exist packed) ----
__device__ __forceinline__ u64 pack2(float lo, float hi) {
    u64 r; asm("mov.b64 %0, {%1,%2};" : "=l"(r) : "f"(lo), "f"(hi)); return r;
}
#define FMA2(d,a,b,c) asm("fma.rn.f32x2 %0,%1,%2,%3;" : "=l"(d) : "l"(a),"l"(b),"l"(c))
#define MUL2(d,a,b)   asm("mul.rn.f32x2 %0,%1,%2;"    : "=l"(d) : "l"(a),"l"(b))
#define UNPACK2(lo,hi,v) asm("mov.b64 {%0,%1}, %2;" : "=f"(lo),"=f"(hi) : "l"(v))

// ============================================================
// Kernel 1: transposes / relayouts. 256 blocks x 256 threads,
// each block = 2 logical 32x32 tiles (two 128-thread groups).
//   logical [0,256):   W[o][i]  -> g_Wt[i][o]
//   logical [256,384): AW[o][e] -> g_AWt[e][o]
//   logical [384,512): PE[i][e] -> g_PE2[e][i] (duplicated u64)
// ============================================================
__global__ __launch_bounds__(256) void kernel_prep(
    const float* __restrict__ W, const float* __restrict__ AW,
    const float* __restrict__ PE) {
    __shared__ float tile[2][32][33];
    const int tid = threadIdx.x;
    const int grp = tid >> 7;            // 0 or 1
    const int t = tid & 127;
    const int tx = t & 31, ty = t >> 5;
    const int blk = blockIdx.x * 2 + grp;
    float (*tl)[33] = tile[grp];

    if (blk < 256) {
        int c = (blk & 15) * 32 + tx;
        int r0 = (blk >> 4) * 32;
#pragma unroll
        for (int j = 0; j < 32; j += 4)
            tl[ty + j][tx] = W[(r0 + ty + j) * IND + c];
        __syncthreads();
        int c2 = (blk >> 4) * 32 + tx;
        int r2 = (blk & 15) * 32;
#pragma unroll
        for (int j = 0; j < 32; j += 4)
            g_Wt[(r2 + ty + j) * OUTD + c2] = tl[tx][ty + j];
    } else if (blk < 384) {
        int tt = blk - 256;
        int o0 = (tt & 15) * 32;
        int e0 = (tt >> 4) * 32;
#pragma unroll
        for (int j = 0; j < 32; j += 4)
            tl[ty + j][tx] = AW[(o0 + ty + j) * ED + e0 + tx];
        __syncthreads();
#pragma unroll
        for (int j = 0; j < 32; j += 4)
            g_AWt[(e0 + ty + j) * OUTD + o0 + tx] = tl[tx][ty + j];
    } else {
        int tt = blk - 384;
        int i0 = (tt & 15) * 32;
        int e0 = (tt >> 4) * 32;
#pragma unroll
        for (int j = 0; j < 32; j += 4)
            tl[ty + j][tx] = PE[(i0 + ty + j) * ED + e0 + tx];
        __syncthreads();
#pragma unroll
        for (int j = 0; j < 32; j += 4) {
            float v = tl[tx][ty + j];
            g_PE2[(e0 + ty + j) * IND + i0 + tx] = pack2(v, v);
        }
    }
}

// ============================================================
// Kernel 2: tiled scores GEMM. scores[i][o] = AB[o] + sum_e PE[i][e]*AWt[e][o]
// (unchanged from round 7 — measured fine)
// ============================================================
__global__ __launch_bounds__(128) void kernel_scores(
    const float* __restrict__ AB) {
    __shared__ float awb[2][32][68];   // [buf][e][o_local], padded
    __shared__ u64 peb[2][32][34];     // [buf][e][i_local] dup, padded

    const int tid = threadIdx.x;
    const int to = tid & 15;           // floats o0 + 4*to .. +3
    const int ti = tid >> 4;           // i0 + 4*ti .. +3
    const int o0 = (blockIdx.x & 7) * 64;
    const int i0 = (blockIdx.x >> 3) * 32;

    const int sr = tid >> 4;           // staging row base [0,8)
    const int sc = tid & 15;           // staging col

    u64 acc[4][2];
    const u64 z = pack2(0.f, 0.f);
#pragma unroll
    for (int ii = 0; ii < 4; ii++) { acc[ii][0] = z; acc[ii][1] = z; }

    float4 qa[4];
    ulonglong2 qp[4];

    auto LDGC = [&](int e0) {
#pragma unroll
        for (int k = 0; k < 4; k++) {
            int row = sr + k * 8;
            qa[k] = *(const float4*)(g_AWt + (e0 + row) * OUTD + o0 + sc * 4);
            qp[k] = *(const ulonglong2*)(g_PE2 + (e0 + row) * IND + i0 + sc * 2);
        }
    };
    auto STSC = [&](int buf) {
#pragma unroll
        for (int k = 0; k < 4; k++) {
            int row = sr + k * 8;
            *(float4*)&awb[buf][row][sc * 4] = qa[k];
            *(ulonglong2*)&peb[buf][row][sc * 2] = qp[k];
        }
    };
    auto COMPUTE = [&](int buf) {
#pragma unroll 4
        for (int e = 0; e < 32; e++) {
            ulonglong2 a = *(const ulonglong2*)&awb[buf][e][4 * to];
            ulonglong2 p01 = *(const ulonglong2*)&peb[buf][e][4 * ti];
            ulonglong2 p23 = *(const ulonglong2*)&peb[buf][e][4 * ti + 2];
            FMA2(acc[0][0], p01.x, a.x, acc[0][0]);
            FMA2(acc[0][1], p01.x, a.y, acc[0][1]);
            FMA2(acc[1][0], p01.y, a.x, acc[1][0]);
            FMA2(acc[1][1], p01.y, a.y, acc[1][1]);
            FMA2(acc[2][0], p23.x, a.x, acc[2][0]);
            FMA2(acc[2][1], p23.x, a.y, acc[2][1]);
            FMA2(acc[3][0], p23.y, a.x, acc[3][0]);
            FMA2(acc[3][1], p23.y, a.y, acc[3][1]);
        }
    };

    LDGC(0);
    STSC(0);
    __syncthreads();
#pragma unroll 1
    for (int c = 0; c < 8; c++) {
        if (c < 7) LDGC(32 * (c + 1));
        COMPUTE(c & 1);
        if (c < 7) {
            STSC((c + 1) & 1);
            __syncthreads();
        }
    }

    float4 bb = *(const float4*)(AB + o0 + 4 * to);
#pragma unroll
    for (int ii = 0; ii < 4; ii++) {
        float f0, f1, f2, f3;
        UNPACK2(f0, f1, acc[ii][0]);
        UNPACK2(f2, f3, acc[ii][1]);
        float4 o4;
        o4.x = f0 + bb.x; o4.y = f1 + bb.y;
        o4.z = f2 + bb.z; o4.w = f3 + bb.w;
        *(float4*)(g_scores + (i0 + 4 * ti + ii) * OUTD + o0 + 4 * to) = o4;
    }
}

// ============================================================
// Kernel 3: LayerNorm -> sigmoid -> write interleaved g_WM float4
// ============================================================
__global__ __launch_bounds__(128) void kernel_lnwm(
    const float* __restrict__ LG, const float* __restrict__ LB) {
    const int tid = threadIdx.x;
    const int i0 = blockIdx.x * 4;
    const int w = tid >> 5, lane = tid & 31;
    __shared__ float mus[4], rss[4];

    {
        const float* row = g_scores + (i0 + w) * OUTD;
        float s = 0.f, s2 = 0.f;
#pragma unroll
        for (int k = 0; k < 16; k++) {
            float v = row[lane + 32 * k];
            s += v; s2 += v * v;
        }
#pragma unroll
        for (int off = 16; off > 0; off >>= 1) {
            s  += __shfl_xor_sync(0xffffffffu, s,  off);
            s2 += __shfl_xor_sync(0xffffffffu, s2, off);
        }
        if (lane == 0) {
            float mu = s * (1.f / OUTD);
            float var = s2 * (1.f / OUTD) - mu * mu;
            mus[w] = mu;
            rss[w] = rsqrtf(var + LN_EPS_C);
        }
    }
    __syncthreads();
#pragma unroll
    for (int ii = 0; ii < 4; ii++) {
        float mu = mus[ii], rs = rss[ii];
        const int i = i0 + ii;
#pragma unroll
        for (int j = 0; j < 2; j++) {
            int p = tid + j * 128;  // o-pair index [0,256)
            float2 s2v = *(const float2*)(g_scores + i * OUTD + 2 * p);
            float2 w2v = *(const float2*)(g_Wt + i * OUTD + 2 * p);
            float glo = LG[2 * p],     blo = LB[2 * p];
            float ghi = LG[2 * p + 1], bhi = LB[2 * p + 1];
            float vlo = (s2v.x - mu) * rs * glo + blo;
            float vhi = (s2v.y - mu) * rs * ghi + bhi;
            float siglo = 1.f / (1.f + __expf(-vlo));
            float sighi = 1.f / (1.f + __expf(-vhi));
            float4 q;
            q.x = w2v.x; q.y = w2v.y;
            q.z = fabsf(w2v.x) * siglo;
            q.w = fabsf(w2v.y) * sighi;
            g_WM[i * (OUTD / 2) + p] = q;
        }
    }
}

// ============================================================
// Kernel 4 (main): out[b,o] = x@Wt + 0.1*(max_i t*M - sum_i t*M)
//
// grid (8 o-tiles of 64, 64 b-tiles of 4), block 256, 4 blocks/SM
// (entire 512-block grid resident in ONE wave: 592 slots).
// g_WM rows read as ulonglong2 -> (w_lo,w_hi)/(m_lo,m_hi) u64s arrive
// pre-packed, no pack movs. 1-i ping-pong prefetch (16 regs).
// ============================================================
#define MAIN_SMEM (4 * IND * 16)  // 32 KB

__global__ __launch_bounds__(256, 4) void kernel_main(
    const float* __restrict__ X, float* __restrict__ out) {
    extern __shared__ char smem_raw[];
    ulonglong2 (*xt)[IND] = (ulonglong2 (*)[IND])smem_raw;  // [4][512]
    float* red = (float*)smem_raw;

    const int tid = threadIdx.x;
    const int to = tid & 15;
    const int si = tid >> 4;        // [0,16), i-chunk of 32
    const int b0 = blockIdx.y * 4;

    for (int idx = tid; idx < 4 * IND; idx += 256) {
        int b = idx >> 9, i = idx & 511;
        float xv = X[(b0 + b) * IND + i];
        float tv = xv * fabsf(xv);
        xt[b][i] = make_ulonglong2(pack2(xv, xv), pack2(tv, tv));
    }
    __syncthreads();

    u64 c[4][2];
    float mxl[4][2], mxh[4][2];
    const u64 z = pack2(0.f, 0.f);
    const u64 n01 = pack2(-DELTA_C, -DELTA_C);
#pragma unroll
    for (int b = 0; b < 4; b++) {
        c[b][0] = z; c[b][1] = z;
        mxl[b][0] = -INFINITY; mxl[b][1] = -INFINITY;
        mxh[b][0] = -INFINITY; mxh[b][1] = -INFINITY;
    }

    const int ib = si * 32;
    // wm row stride = OUTD/2 = 256 ulonglong2; o-pair a = bx*32+to, b = +16
    const ulonglong2* __restrict__ wm =
        (const ulonglong2*)g_WM + blockIdx.x * 32 + to;

    // compute one i using (qa = pair a, qb = pair b)
    auto COMP = [&](ulonglong2 qa, ulonglong2 qb, int i) {
#pragma unroll
        for (int b = 0; b < 4; b++) {
            ulonglong2 v = xt[b][i];
            FMA2(c[b][0], v.x, qa.x, c[b][0]);
            u64 pa; MUL2(pa, v.y, qa.y);
            FMA2(c[b][0], pa, n01, c[b][0]);
            float palo, pahi; UNPACK2(palo, pahi, pa);
            mxl[b][0] = fmaxf(mxl[b][0], palo);
            mxh[b][0] = fmaxf(mxh[b][0], pahi);
            FMA2(c[b][1], v.x, qb.x, c[b][1]);
            u64 pb; MUL2(pb, v.y, qb.y);
            FMA2(c[b][1], pb, n01, c[b][1]);
            float pblo, pbhi; UNPACK2(pblo, pbhi, pb);
            mxl[b][1] = fmaxf(mxl[b][1], pblo);
            mxh[b][1] = fmaxf(mxh[b][1], pbhi);
        }
    };

    ulonglong2 qa, qb, na, nb;
    qa = wm[(u64)ib * 256];
    qb = wm[(u64)ib * 256 + 16];
#pragma unroll 1
    for (int g = 0; g < 16; g++) {
        const int i = ib + 2 * g;
        na = wm[(u64)(i + 1) * 256];          // prefetch odd i
        nb = wm[(u64)(i + 1) * 256 + 16];
        COMP(qa, qb, i);                       // even i
        if (g < 15) {
            qa = wm[(u64)(i + 2) * 256];      // prefetch next even
            qb = wm[(u64)(i + 2) * 256 + 16];
        }
        COMP(na, nb, i + 1);                   // odd i
    }

    __syncthreads();  // xt done; reuse as reduction buffer

#define RIDX(k, b, j, s, t) ((((((k) * 4 + (b)) * 2 + (j)) * 16 + (s)) * 16) + (t))
#pragma unroll
    for (int b = 0; b < 4; b++) {
#pragma unroll
        for (int j = 0; j < 2; j++) {
            float clo, chi;
            UNPACK2(clo, chi, c[b][j]);
            red[RIDX(0, b, j, si, to)] = clo;
            red[RIDX(1, b, j, si, to)] = chi;
            red[RIDX(2, b, j, si, to)] = mxl[b][j];
            red[RIDX(3, b, j, si, to)] = mxh[b][j];
        }
    }
    __syncthreads();

    if (tid < 128) {
        const int b2 = tid >> 5;
        const int pl = tid & 31;
        const int j2 = pl >> 4;
        const int to2 = pl & 15;
        float slo = 0.f, shi = 0.f, Mlo = -INFINITY, Mhi = -INFINITY;
#pragma unroll
        for (int s = 0; s < 16; s++) {
            slo += red[RIDX(0, b2, j2, s, to2)];
            shi += red[RIDX(1, b2, j2, s, to2)];
            Mlo = fmaxf(Mlo, red[RIDX(2, b2, j2, s, to2)]);
            Mhi = fmaxf(Mhi, red[RIDX(3, b2, j2, s, to2)]);
        }
        float2 r;
        r.x = slo + DELTA_C * Mlo;
        r.y = shi + DELTA_C * Mhi;
        *(float2*)(out + (b0 + b2) * OUTD + blockIdx.x * 64 + pl * 2) = r;
    }
#undef RIDX
}

// ============================================================
extern "C" void kernel_launch(void* const* d_in, const int* in_sizes, int n_in,
                              void* d_out, int out_size) {
    const float* x  = (const float*)d_in[0];
    const float* w  = (const float*)d_in[1];
    const float* pe = (const float*)d_in[2];
    const float* aw = (const float*)d_in[3];
    const float* ab = (const float*)d_in[4];
    const float* lg = (const float*)d_in[5];
    const float* lb = (const float*)d_in[6];
    float* out = (float*)d_out;

    kernel_prep<<<256, 256>>>(w, aw, pe);
    kernel_scores<<<128, 128>>>(ab);
    kernel_lnwm<<<128, 128>>>(lg, lb);
    kernel_main<<<dim3(8, 64), 256, MAIN_SMEM>>>(x, out);
}